// round 3
// baseline (speedup 1.0000x reference)
#include <cuda_runtime.h>
#include <math.h>
#include <stdint.h>

#define B_    8
#define SEQ   1024
#define DIM_  768
#define NH    12
#define HD_   64
#define QKVD  2304
#define SCALE_ 0.125f
#define EPS_   1e-6f
#define EPSN_  9.765625e-10f   /* EPS_/1024 */
#define LOG2E_ 1.4426950408889634f

// Scratch (no allocations allowed)
__device__ float g_qkv[(size_t)B_ * SEQ * QKVD];
__device__ float g_att[(size_t)B_ * SEQ * DIM_];

// f32 -> tf32 round-to-nearest (HW mma truncates otherwise)
__device__ __forceinline__ float f2tff(float x) {
    unsigned u;
    asm("cvt.rna.tf32.f32 %0, %1;" : "=r"(u) : "f"(x));
    return __uint_as_float(u);
}
__device__ __forceinline__ float ex2f(float x) {
    float y;
    asm("ex2.approx.f32 %0, %1;" : "=f"(y) : "f"(x));
    return y;
}
__device__ __forceinline__ float4 cvt4(float4 v) {
    return make_float4(f2tff(v.x), f2tff(v.y), f2tff(v.z), f2tff(v.w));
}
// m16n8k8 row.col tf32 MMA, fp32 accumulate (D += A*B)
__device__ __forceinline__ void mma8(float d[4], const float a[4], const float b[2]) {
    asm volatile(
        "mma.sync.aligned.m16n8k8.row.col.f32.tf32.tf32.f32 "
        "{%0,%1,%2,%3}, {%4,%5,%6,%7}, {%8,%9}, {%0,%1,%2,%3};"
        : "+f"(d[0]), "+f"(d[1]), "+f"(d[2]), "+f"(d[3])
        : "r"(__float_as_uint(a[0])), "r"(__float_as_uint(a[1])),
          "r"(__float_as_uint(a[2])), "r"(__float_as_uint(a[3])),
          "r"(__float_as_uint(b[0])), "r"(__float_as_uint(b[1])));
}

// ---------------------------------------------------------------------------
// tf32 GEMM (NT), 2-stage smem ping-pong: C[M,N] = A[M,K] @ W[N,K]^T (+bias).
// 128x128x32 tiles, 8 warps (2x4), warp tile 64x32. Row stride 36 words:
// scalar fragment LDS banks (4g+q) conflict-free; float4 STS phase-coalesced.
// ---------------------------------------------------------------------------
#define GST 4608   /* 128*36 floats per operand per stage */
__global__ __launch_bounds__(256) void gemm_tf32(
    const float* __restrict__ A, const float* __restrict__ W,
    const float* __restrict__ bias, float* __restrict__ C,
    int M, int N, int K)
{
    extern __shared__ float gsm[];
    const int tid = threadIdx.x;
    const int lane = tid & 31, wid = tid >> 5;
    const int wm = (wid >> 2) * 64, wn = (wid & 3) * 32;
    const int g = lane >> 2, q = lane & 3;
    const int bm = blockIdx.y * 128, bn = blockIdx.x * 128;
    const int lr = tid >> 3, lc = (tid & 7) << 2;

    float acc[4][4][4];
#pragma unroll
    for (int i = 0; i < 4; i++)
#pragma unroll
        for (int j = 0; j < 4; j++)
#pragma unroll
            for (int r = 0; r < 4; r++) acc[i][j][r] = 0.f;

    const float* Ap = A + (size_t)(bm + lr) * K + lc;
    const float* Wp = W + (size_t)(bn + lr) * K + lc;

    float4 ra[4], rw[4];
#pragma unroll
    for (int s = 0; s < 4; s++) {
        ra[s] = *(const float4*)(Ap + (size_t)s * 32 * K);
        rw[s] = *(const float4*)(Wp + (size_t)s * 32 * K);
    }
    {
        float* As0 = gsm; float* Ws0 = gsm + GST;
#pragma unroll
        for (int s = 0; s < 4; s++) {
            *(float4*)&As0[(lr + s*32)*36 + lc] = cvt4(ra[s]);
            *(float4*)&Ws0[(lr + s*32)*36 + lc] = cvt4(rw[s]);
        }
    }
#pragma unroll
    for (int s = 0; s < 4; s++) {
        ra[s] = *(const float4*)(Ap + (size_t)s * 32 * K + 32);
        rw[s] = *(const float4*)(Wp + (size_t)s * 32 * K + 32);
    }
    __syncthreads();

    int p = 0;
    for (int k0 = 0; k0 < K; k0 += 32) {
        const float* Asp = gsm + p * 2 * GST;
        const float* Wsp = Asp + GST;
        if (k0 + 32 < K) {
            float* Asn = gsm + (p ^ 1) * 2 * GST;
            float* Wsn = Asn + GST;
#pragma unroll
            for (int s = 0; s < 4; s++) {
                *(float4*)&Asn[(lr + s*32)*36 + lc] = cvt4(ra[s]);
                *(float4*)&Wsn[(lr + s*32)*36 + lc] = cvt4(rw[s]);
            }
        }
        if (k0 + 64 < K) {
#pragma unroll
            for (int s = 0; s < 4; s++) {
                ra[s] = *(const float4*)(Ap + (size_t)s * 32 * K + k0 + 64);
                rw[s] = *(const float4*)(Wp + (size_t)s * 32 * K + k0 + 64);
            }
        }
#pragma unroll
        for (int kk = 0; kk < 32; kk += 8) {
            float af[4][4], bf[4][2];
#pragma unroll
            for (int mt = 0; mt < 4; mt++) {
                int r = wm + mt*16 + g;
                af[mt][0] = Asp[r*36 + kk+q];     af[mt][1] = Asp[(r+8)*36 + kk+q];
                af[mt][2] = Asp[r*36 + kk+q+4];   af[mt][3] = Asp[(r+8)*36 + kk+q+4];
            }
#pragma unroll
            for (int nt = 0; nt < 4; nt++) {
                int n = wn + nt*8 + g;
                bf[nt][0] = Wsp[n*36 + kk+q];     bf[nt][1] = Wsp[n*36 + kk+q+4];
            }
#pragma unroll
            for (int mt = 0; mt < 4; mt++)
#pragma unroll
                for (int nt = 0; nt < 4; nt++)
                    mma8(acc[mt][nt], af[mt], bf[nt]);
        }
        __syncthreads();
        p ^= 1;
    }

#pragma unroll
    for (int mt = 0; mt < 4; mt++) {
        int r0 = bm + wm + mt*16 + g;
#pragma unroll
        for (int nt = 0; nt < 4; nt++) {
            int c = bn + wn + nt*8 + 2*q;
            float b0 = bias ? bias[c]   : 0.f;
            float b1 = bias ? bias[c+1] : 0.f;
            *(float2*)&C[(size_t)r0 * N + c] =
                make_float2(acc[mt][nt][0] + b0, acc[mt][nt][1] + b1);
            *(float2*)&C[(size_t)(r0+8) * N + c] =
                make_float2(acc[mt][nt][2] + b0, acc[mt][nt][3] + b1);
        }
    }
}

// ---------------------------------------------------------------------------
// Fused attention v3: register-resident flash softmax.
// Block = 128 q-rows x (head, batch); warp owns 16 rows x full 64-wide KV tile
// -> row reductions are intra-quad shuffles only. P C-frag -> A-frag via quad
// shuffles (no smem round trip). K/V double-buffered; ONE sync per KV tile.
// P' = exp(s-m)*policy + EPS/N; out = (P'@V)/rowsum(P') == reference exactly.
// ---------------------------------------------------------------------------
__global__ __launch_bounds__(256, 2) void attn_tf32(const float* __restrict__ policy)
{
    extern __shared__ float sm[];
    float (*Qs)[68]      = (float(*)[68])(sm);                       // 128x68
    float (*Ks)[64][68]  = (float(*)[64][68])(sm + 128*68);          // [2][64][68]
    float (*Vs)[64][68]  = (float(*)[64][68])(sm + 128*68 + 2*64*68);
    float (*pol)[64]     = (float(*)[64])(sm + 128*68 + 4*64*68);    // [2][64]

    const int it = blockIdx.x, h = blockIdx.y, b = blockIdx.z;
    const int tid = threadIdx.x, lane = tid & 31, wid = tid >> 5;
    const int g = lane >> 2, q = lane & 3;
    const int rowA = wid * 16 + g;
    const int qrow0 = it * 128;
    const int grow0 = qrow0 + rowA;   // rows grow0 and grow0+8

    // ---- load Q tile (scaled, tf32) ----
    {
        const size_t qb = ((size_t)(b * SEQ) + qrow0) * QKVD + h * HD_;
#pragma unroll
        for (int p = 0; p < 8; p++) {
            int idx = tid + p * 256;
            int r = idx >> 4, c = (idx & 15) * 4;
            float4 v = *(const float4*)&g_qkv[qb + (size_t)r * QKVD + c];
            *(float4*)&Qs[r][c] = make_float4(
                f2tff(v.x * SCALE_), f2tff(v.y * SCALE_),
                f2tff(v.z * SCALE_), f2tff(v.w * SCALE_));
        }
    }

    const int ldr = tid >> 4;            // 0..15
    const int ldc = (tid & 15) * 4;      // 0..60
    const float* kb0 = g_qkv + (size_t)(b * SEQ) * QKVD + DIM_ + h * HD_
                       + (size_t)ldr * QKVD + ldc;

    float4 rK[4], rV[4];
#pragma unroll
    for (int p = 0; p < 4; p++) {         // tile 0
        const float* src = kb0 + (size_t)(p * 16) * QKVD;
        rK[p] = *(const float4*)(src);
        rV[p] = *(const float4*)(src + DIM_);
    }
#pragma unroll
    for (int p = 0; p < 4; p++) {
        int r = ldr + p * 16;
        *(float4*)&Ks[0][r][ldc] = cvt4(rK[p]);
        *(float4*)&Vs[0][r][ldc] = cvt4(rV[p]);
    }
    if (tid < 64) pol[0][tid] = policy[(size_t)b * SEQ + tid];
#pragma unroll
    for (int p = 0; p < 4; p++) {         // prefetch tile 1
        const float* src = kb0 + (size_t)(64 + p * 16) * QKVD;
        rK[p] = *(const float4*)(src);
        rV[p] = *(const float4*)(src + DIM_);
    }
    __syncthreads();

    float o[8][4];
#pragma unroll
    for (int dt = 0; dt < 8; dt++)
#pragma unroll
        for (int r = 0; r < 4; r++) o[dt][r] = 0.f;
    float m0 = -3.0e38f, m1 = -3.0e38f, l0 = 0.f, l1 = 0.f;

    for (int jt = 0; jt < 16; jt++) {
        const int bf_ = jt & 1;

        // ---- S = Q @ K^T : warp computes 16 x 64 ----
        float s[8][4];
#pragma unroll
        for (int nt = 0; nt < 8; nt++)
#pragma unroll
            for (int r = 0; r < 4; r++) s[nt][r] = 0.f;
#pragma unroll
        for (int kk = 0; kk < 64; kk += 8) {
            float a[4];
            a[0] = Qs[rowA][kk+q];     a[1] = Qs[rowA+8][kk+q];
            a[2] = Qs[rowA][kk+q+4];   a[3] = Qs[rowA+8][kk+q+4];
#pragma unroll
            for (int nt = 0; nt < 8; nt++) {
                float bb[2];
                bb[0] = Ks[bf_][nt*8+g][kk+q];
                bb[1] = Ks[bf_][nt*8+g][kk+q+4];
                mma8(s[nt], a, bb);
            }
        }

        // ---- row max (intra-quad only: warp owns full rows) ----
        float mt0 = -3.0e38f, mt1 = -3.0e38f;
#pragma unroll
        for (int nt = 0; nt < 8; nt++) {
            mt0 = fmaxf(mt0, fmaxf(s[nt][0], s[nt][1]));
            mt1 = fmaxf(mt1, fmaxf(s[nt][2], s[nt][3]));
        }
        mt0 = fmaxf(mt0, __shfl_xor_sync(0xffffffffu, mt0, 1));
        mt0 = fmaxf(mt0, __shfl_xor_sync(0xffffffffu, mt0, 2));
        mt1 = fmaxf(mt1, __shfl_xor_sync(0xffffffffu, mt1, 1));
        mt1 = fmaxf(mt1, __shfl_xor_sync(0xffffffffu, mt1, 2));
        float mn0 = fmaxf(m0, mt0), mn1 = fmaxf(m1, mt1);
        float c0 = ex2f((m0 - mn0) * LOG2E_);
        float c1 = ex2f((m1 - mn1) * LOG2E_);
        m0 = mn0; m1 = mn1;
        const float a0 = mn0 * LOG2E_, a1 = mn1 * LOG2E_;

        // ---- p = exp(s-m)*policy + EPS/N ; sums; tf32-round into s ----
        float sum0 = 0.f, sum1 = 0.f;
#pragma unroll
        for (int nt = 0; nt < 8; nt++) {
            int cl = nt*8 + 2*q;
            int jg = jt*64 + cl;
            float pf0 = pol[bf_][cl], pf1 = pol[bf_][cl+1];
            float p00 = ex2f(fmaf(s[nt][0], LOG2E_, -a0))
                        * ((jg   == grow0)     ? 1.f : pf0) + EPSN_;
            float p01 = ex2f(fmaf(s[nt][1], LOG2E_, -a0))
                        * ((jg+1 == grow0)     ? 1.f : pf1) + EPSN_;
            float p10 = ex2f(fmaf(s[nt][2], LOG2E_, -a1))
                        * ((jg   == grow0 + 8) ? 1.f : pf0) + EPSN_;
            float p11 = ex2f(fmaf(s[nt][3], LOG2E_, -a1))
                        * ((jg+1 == grow0 + 8) ? 1.f : pf1) + EPSN_;
            sum0 += p00 + p01;  sum1 += p10 + p11;
            s[nt][0] = f2tff(p00); s[nt][1] = f2tff(p01);
            s[nt][2] = f2tff(p10); s[nt][3] = f2tff(p11);
        }
        sum0 += __shfl_xor_sync(0xffffffffu, sum0, 1);
        sum0 += __shfl_xor_sync(0xffffffffu, sum0, 2);
        sum1 += __shfl_xor_sync(0xffffffffu, sum1, 1);
        sum1 += __shfl_xor_sync(0xffffffffu, sum1, 2);
        l0 = l0 * c0 + sum0;
        l1 = l1 * c1 + sum1;
#pragma unroll
        for (int dt = 0; dt < 8; dt++) {
            o[dt][0] *= c0; o[dt][1] *= c0;
            o[dt][2] *= c1; o[dt][3] *= c1;
        }

        // ---- PV: C-frag -> A-frag via quad shuffles, then mma ----
        const int srcl = (lane & ~3) | (q >> 1);
#pragma unroll
        for (int ck = 0; ck < 8; ck++) {
            float u0 = __shfl_sync(0xffffffffu, s[ck][0], srcl);
            float u1 = __shfl_sync(0xffffffffu, s[ck][1], srcl);
            float u2 = __shfl_sync(0xffffffffu, s[ck][2], srcl);
            float u3 = __shfl_sync(0xffffffffu, s[ck][3], srcl);
            float w0 = __shfl_sync(0xffffffffu, s[ck][0], srcl + 2);
            float w1 = __shfl_sync(0xffffffffu, s[ck][1], srcl + 2);
            float w2 = __shfl_sync(0xffffffffu, s[ck][2], srcl + 2);
            float w3 = __shfl_sync(0xffffffffu, s[ck][3], srcl + 2);
            float aP[4];
            aP[0] = (q & 1) ? u1 : u0;   // P[r0][ck*8+q]
            aP[1] = (q & 1) ? u3 : u2;   // P[r1][ck*8+q]
            aP[2] = (q & 1) ? w1 : w0;   // P[r0][ck*8+q+4]
            aP[3] = (q & 1) ? w3 : w2;   // P[r1][ck*8+q+4]
#pragma unroll
            for (int dt = 0; dt < 8; dt++) {
                float bb[2];
                bb[0] = Vs[bf_][ck*8+q][dt*8+g];
                bb[1] = Vs[bf_][ck*8+q+4][dt*8+g];
                mma8(o[dt], aP, bb);
            }
        }

        // ---- stage next tile; single sync per iteration ----
        if (jt < 15) {
#pragma unroll
            for (int p = 0; p < 4; p++) {
                int r = ldr + p * 16;
                *(float4*)&Ks[bf_ ^ 1][r][ldc] = cvt4(rK[p]);
                *(float4*)&Vs[bf_ ^ 1][r][ldc] = cvt4(rV[p]);
            }
            if (tid < 64)
                pol[bf_ ^ 1][tid] = policy[(size_t)b * SEQ + (jt+1) * 64 + tid];
            if (jt < 14) {
                const float* src0 = kb0 + (size_t)((jt + 2) * 64) * QKVD;
#pragma unroll
                for (int p = 0; p < 4; p++) {
                    const float* src = src0 + (size_t)(p * 16) * QKVD;
                    rK[p] = *(const float4*)(src);
                    rV[p] = *(const float4*)(src + DIM_);
                }
            }
            __syncthreads();
        }
    }

    // ---- epilogue ----
    const float inv0 = 1.f / l0, inv1 = 1.f / l1;
    const size_t ro0 = ((size_t)(b * SEQ) + grow0) * DIM_ + h * HD_;
#pragma unroll
    for (int dt = 0; dt < 8; dt++) {
        int c = dt*8 + 2*q;
        *(float2*)&g_att[ro0 + c] =
            make_float2(o[dt][0] * inv0, o[dt][1] * inv0);
        *(float2*)&g_att[ro0 + (size_t)8 * DIM_ + c] =
            make_float2(o[dt][2] * inv1, o[dt][3] * inv1);
    }
}

// ---------------------------------------------------------------------------
extern "C" void kernel_launch(void* const* d_in, const int* in_sizes, int n_in,
                              void* d_out, int out_size)
{
    const float* x      = (const float*)d_in[0];
    const float* policy = (const float*)d_in[1];
    const float* qkv_w  = (const float*)d_in[2];
    const float* proj_w = (const float*)d_in[3];
    const float* proj_b = (const float*)d_in[4];
    float* out = (float*)d_out;

    float* qkv_buf; float* att_buf;
    cudaGetSymbolAddress((void**)&qkv_buf, g_qkv);
    cudaGetSymbolAddress((void**)&att_buf, g_att);

    const int gemm_smem = 4 * GST * (int)sizeof(float);                 // 73728
    const int attn_smem = (128*68 + 4*64*68 + 2*64) * (int)sizeof(float); // 104960
    cudaFuncSetAttribute(gemm_tf32,
                         cudaFuncAttributeMaxDynamicSharedMemorySize, gemm_smem);
    cudaFuncSetAttribute(attn_tf32,
                         cudaFuncAttributeMaxDynamicSharedMemorySize, attn_smem);

    // 1) QKV = x @ qkv_w^T
    gemm_tf32<<<dim3(QKVD/128, (B_*SEQ)/128), 256, gemm_smem>>>(
        x, qkv_w, nullptr, qkv_buf, B_*SEQ, QKVD, DIM_);
    // 2) Fused policy-softmax attention -> g_att [B*N, H*HD]
    attn_tf32<<<dim3(SEQ/128, NH, B_), 256, attn_smem>>>(policy);
    // 3) out = att @ proj_w^T + proj_b
    gemm_tf32<<<dim3(DIM_/128, (B_*SEQ)/128), 256, gemm_smem>>>(
        att_buf, proj_w, proj_b, out, B_*SEQ, DIM_, DIM_);
}

// round 4
// speedup vs baseline: 1.7071x; 1.7071x over previous
#include <cuda_runtime.h>
#include <math.h>
#include <stdint.h>

#define B_    8
#define SEQ   1024
#define DIM_  768
#define NH    12
#define HD_   64
#define QKVD  2304
#define SCALE_ 0.125f
#define EPS_   1e-6f
#define EPSN_  9.765625e-10f   /* EPS_/1024 */
#define LOG2E_ 1.4426950408889634f

// Scratch (no allocations allowed)
__device__ float g_qkv[(size_t)B_ * SEQ * QKVD];
__device__ float g_att[(size_t)B_ * SEQ * DIM_];

// f32 -> tf32 round-to-nearest (HW mma truncates otherwise)
__device__ __forceinline__ float f2tff(float x) {
    unsigned u;
    asm("cvt.rna.tf32.f32 %0, %1;" : "=r"(u) : "f"(x));
    return __uint_as_float(u);
}
__device__ __forceinline__ float ex2f(float x) {
    float y;
    asm("ex2.approx.f32 %0, %1;" : "=f"(y) : "f"(x));
    return y;
}
__device__ __forceinline__ float4 cvt4(float4 v) {
    return make_float4(f2tff(v.x), f2tff(v.y), f2tff(v.z), f2tff(v.w));
}
// m16n8k8 row.col tf32 MMA, fp32 accumulate (D += A*B)
__device__ __forceinline__ void mma8(float d[4], const float a[4], const float b[2]) {
    asm volatile(
        "mma.sync.aligned.m16n8k8.row.col.f32.tf32.tf32.f32 "
        "{%0,%1,%2,%3}, {%4,%5,%6,%7}, {%8,%9}, {%0,%1,%2,%3};"
        : "+f"(d[0]), "+f"(d[1]), "+f"(d[2]), "+f"(d[3])
        : "r"(__float_as_uint(a[0])), "r"(__float_as_uint(a[1])),
          "r"(__float_as_uint(a[2])), "r"(__float_as_uint(a[3])),
          "r"(__float_as_uint(b[0])), "r"(__float_as_uint(b[1])));
}

// ---------------------------------------------------------------------------
// tf32 GEMM (NT) — EXACT Round-2 version (proven 153 TF/s).
// 128x128x32 tiles, 8 warps (2x4), warp tile 64x32, row stride 36.
// ---------------------------------------------------------------------------
__global__ __launch_bounds__(256) void gemm_tf32(
    const float* __restrict__ A, const float* __restrict__ W,
    const float* __restrict__ bias, float* __restrict__ C,
    int M, int N, int K)
{
    __shared__ float As[128][36];
    __shared__ float Ws[128][36];
    const int tid = threadIdx.x;
    const int lane = tid & 31, wid = tid >> 5;
    const int wm = (wid >> 2) * 64, wn = (wid & 3) * 32;
    const int g = lane >> 2, q = lane & 3;
    const int bm = blockIdx.y * 128, bn = blockIdx.x * 128;
    const int lr = tid >> 3, lc = (tid & 7) << 2;

    float acc[4][4][4];
#pragma unroll
    for (int i = 0; i < 4; i++)
#pragma unroll
        for (int j = 0; j < 4; j++)
#pragma unroll
            for (int r = 0; r < 4; r++) acc[i][j][r] = 0.f;

    const float* Ap = A + (size_t)(bm + lr) * K + lc;
    const float* Wp = W + (size_t)(bn + lr) * K + lc;

    float4 ra[4], rw[4];
#pragma unroll
    for (int s = 0; s < 4; s++) {
        ra[s] = *(const float4*)(Ap + (size_t)s * 32 * K);
        rw[s] = *(const float4*)(Wp + (size_t)s * 32 * K);
    }

    for (int k0 = 0; k0 < K; k0 += 32) {
#pragma unroll
        for (int s = 0; s < 4; s++) {
            As[lr + s*32][lc+0] = f2tff(ra[s].x); As[lr + s*32][lc+1] = f2tff(ra[s].y);
            As[lr + s*32][lc+2] = f2tff(ra[s].z); As[lr + s*32][lc+3] = f2tff(ra[s].w);
            Ws[lr + s*32][lc+0] = f2tff(rw[s].x); Ws[lr + s*32][lc+1] = f2tff(rw[s].y);
            Ws[lr + s*32][lc+2] = f2tff(rw[s].z); Ws[lr + s*32][lc+3] = f2tff(rw[s].w);
        }
        __syncthreads();
        if (k0 + 32 < K) {
#pragma unroll
            for (int s = 0; s < 4; s++) {
                ra[s] = *(const float4*)(Ap + (size_t)s * 32 * K + k0 + 32);
                rw[s] = *(const float4*)(Wp + (size_t)s * 32 * K + k0 + 32);
            }
        }
#pragma unroll
        for (int kk = 0; kk < 32; kk += 8) {
            float af[4][4], bf[4][2];
#pragma unroll
            for (int mt = 0; mt < 4; mt++) {
                int r = wm + mt*16 + g;
                af[mt][0] = As[r][kk+q];     af[mt][1] = As[r+8][kk+q];
                af[mt][2] = As[r][kk+q+4];   af[mt][3] = As[r+8][kk+q+4];
            }
#pragma unroll
            for (int nt = 0; nt < 4; nt++) {
                int n = wn + nt*8 + g;
                bf[nt][0] = Ws[n][kk+q];     bf[nt][1] = Ws[n][kk+q+4];
            }
#pragma unroll
            for (int mt = 0; mt < 4; mt++)
#pragma unroll
                for (int nt = 0; nt < 4; nt++)
                    mma8(acc[mt][nt], af[mt], bf[nt]);
        }
        __syncthreads();
    }

#pragma unroll
    for (int mt = 0; mt < 4; mt++) {
        int r0 = bm + wm + mt*16 + g;
#pragma unroll
        for (int nt = 0; nt < 4; nt++) {
            int c = bn + wn + nt*8 + 2*q;
            float b0 = bias ? bias[c]   : 0.f;
            float b1 = bias ? bias[c+1] : 0.f;
            *(float2*)&C[(size_t)r0 * N + c] =
                make_float2(acc[mt][nt][0] + b0, acc[mt][nt][1] + b1);
            *(float2*)&C[(size_t)(r0+8) * N + c] =
                make_float2(acc[mt][nt][2] + b0, acc[mt][nt][3] + b1);
        }
    }
}

// ---------------------------------------------------------------------------
// Fused attention v4: register-resident flash softmax, single-buffered K/V,
// no register prefetch (R3's spill source removed), 2 CTAs/SM for latency
// hiding. Warp owns 16 q-rows x full 64-wide KV tile -> row reductions are
// intra-quad shuffles only; P C-frag -> A-frag via quad shuffles.
// Smem: Qs/Ks stride 68 (A/K-frag banks 4g+q unique), Vs stride 72
// (V B-frag banks 8q+g unique). ~70.9KB -> 2 CTAs/SM.
// P' = exp(s-m)*policy + EPS/N; out = (P'@V)/rowsum(P') == reference exactly.
// ---------------------------------------------------------------------------
__global__ __launch_bounds__(256, 2) void attn_tf32(const float* __restrict__ policy)
{
    extern __shared__ float sm[];
    float (*Qs)[68] = (float(*)[68])(sm);                    // 128x68
    float (*Ks)[68] = (float(*)[68])(sm + 128*68);           // 64x68
    float (*Vs)[72] = (float(*)[72])(sm + 128*68 + 64*68);   // 64x72
    float* pol      = sm + 128*68 + 64*68 + 64*72;           // 64

    const int it = blockIdx.x, h = blockIdx.y, b = blockIdx.z;
    const int tid = threadIdx.x, lane = tid & 31, wid = tid >> 5;
    const int g = lane >> 2, q = lane & 3;
    const int rowA = wid * 16 + g;
    const int qrow0 = it * 128;
    const int grow0 = qrow0 + rowA;   // rows grow0 and grow0+8

    // ---- load Q tile (scaled, tf32) ----
    {
        const size_t qb = ((size_t)(b * SEQ) + qrow0) * QKVD + h * HD_;
#pragma unroll
        for (int p = 0; p < 8; p++) {
            int idx = tid + p * 256;
            int r = idx >> 4, c = (idx & 15) * 4;
            float4 v = *(const float4*)&g_qkv[qb + (size_t)r * QKVD + c];
            *(float4*)&Qs[r][c] = make_float4(
                f2tff(v.x * SCALE_), f2tff(v.y * SCALE_),
                f2tff(v.z * SCALE_), f2tff(v.w * SCALE_));
        }
    }

    const int ldr = tid >> 4;            // 0..15
    const int ldc = (tid & 15) * 4;      // 0..60
    const float* kb0 = g_qkv + (size_t)(b * SEQ) * QKVD + DIM_ + h * HD_
                       + (size_t)ldr * QKVD + ldc;

    // ---- tile 0 K/V straight to smem ----
#pragma unroll
    for (int p = 0; p < 4; p++) {
        const float* src = kb0 + (size_t)(p * 16) * QKVD;
        int r = ldr + p * 16;
        *(float4*)&Ks[r][ldc] = cvt4(*(const float4*)(src));
        *(float4*)&Vs[r][ldc] = cvt4(*(const float4*)(src + DIM_));
    }
    if (tid < 64) pol[tid] = policy[(size_t)b * SEQ + tid];
    __syncthreads();

    float o[8][4];
#pragma unroll
    for (int dt = 0; dt < 8; dt++)
#pragma unroll
        for (int r = 0; r < 4; r++) o[dt][r] = 0.f;
    float m0 = -3.0e38f, m1 = -3.0e38f, l0 = 0.f, l1 = 0.f;

    for (int jt = 0; jt < 16; jt++) {
        // ---- S = Q @ K^T : warp computes 16 x 64 ----
        float s[8][4];
#pragma unroll
        for (int nt = 0; nt < 8; nt++)
#pragma unroll
            for (int r = 0; r < 4; r++) s[nt][r] = 0.f;
#pragma unroll
        for (int kk = 0; kk < 64; kk += 8) {
            float a[4];
            a[0] = Qs[rowA][kk+q];     a[1] = Qs[rowA+8][kk+q];
            a[2] = Qs[rowA][kk+q+4];   a[3] = Qs[rowA+8][kk+q+4];
#pragma unroll
            for (int nt = 0; nt < 8; nt++) {
                float bb[2];
                bb[0] = Ks[nt*8+g][kk+q];
                bb[1] = Ks[nt*8+g][kk+q+4];
                mma8(s[nt], a, bb);
            }
        }

        // ---- row max (intra-quad only) ----
        float mt0 = -3.0e38f, mt1 = -3.0e38f;
#pragma unroll
        for (int nt = 0; nt < 8; nt++) {
            mt0 = fmaxf(mt0, fmaxf(s[nt][0], s[nt][1]));
            mt1 = fmaxf(mt1, fmaxf(s[nt][2], s[nt][3]));
        }
        mt0 = fmaxf(mt0, __shfl_xor_sync(0xffffffffu, mt0, 1));
        mt0 = fmaxf(mt0, __shfl_xor_sync(0xffffffffu, mt0, 2));
        mt1 = fmaxf(mt1, __shfl_xor_sync(0xffffffffu, mt1, 1));
        mt1 = fmaxf(mt1, __shfl_xor_sync(0xffffffffu, mt1, 2));
        float mn0 = fmaxf(m0, mt0), mn1 = fmaxf(m1, mt1);
        float c0 = ex2f((m0 - mn0) * LOG2E_);
        float c1 = ex2f((m1 - mn1) * LOG2E_);
        m0 = mn0; m1 = mn1;
        const float a0 = mn0 * LOG2E_, a1 = mn1 * LOG2E_;

        // ---- p = exp(s-m)*policy + EPS/N ; sums; tf32-round into s ----
        float sum0 = 0.f, sum1 = 0.f;
#pragma unroll
        for (int nt = 0; nt < 8; nt++) {
            int cl = nt*8 + 2*q;
            int jg = jt*64 + cl;
            float pf0 = pol[cl], pf1 = pol[cl+1];
            float p00 = ex2f(fmaf(s[nt][0], LOG2E_, -a0))
                        * ((jg   == grow0)     ? 1.f : pf0) + EPSN_;
            float p01 = ex2f(fmaf(s[nt][1], LOG2E_, -a0))
                        * ((jg+1 == grow0)     ? 1.f : pf1) + EPSN_;
            float p10 = ex2f(fmaf(s[nt][2], LOG2E_, -a1))
                        * ((jg   == grow0 + 8) ? 1.f : pf0) + EPSN_;
            float p11 = ex2f(fmaf(s[nt][3], LOG2E_, -a1))
                        * ((jg+1 == grow0 + 8) ? 1.f : pf1) + EPSN_;
            sum0 += p00 + p01;  sum1 += p10 + p11;
            s[nt][0] = f2tff(p00); s[nt][1] = f2tff(p01);
            s[nt][2] = f2tff(p10); s[nt][3] = f2tff(p11);
        }
        sum0 += __shfl_xor_sync(0xffffffffu, sum0, 1);
        sum0 += __shfl_xor_sync(0xffffffffu, sum0, 2);
        sum1 += __shfl_xor_sync(0xffffffffu, sum1, 1);
        sum1 += __shfl_xor_sync(0xffffffffu, sum1, 2);
        l0 = l0 * c0 + sum0;
        l1 = l1 * c1 + sum1;
#pragma unroll
        for (int dt = 0; dt < 8; dt++) {
            o[dt][0] *= c0; o[dt][1] *= c0;
            o[dt][2] *= c1; o[dt][3] *= c1;
        }

        // ---- PV: C-frag -> A-frag via quad shuffles, then mma ----
        const int srcl = (lane & ~3) | (q >> 1);
#pragma unroll
        for (int ck = 0; ck < 8; ck++) {
            float u0 = __shfl_sync(0xffffffffu, s[ck][0], srcl);
            float u1 = __shfl_sync(0xffffffffu, s[ck][1], srcl);
            float u2 = __shfl_sync(0xffffffffu, s[ck][2], srcl);
            float u3 = __shfl_sync(0xffffffffu, s[ck][3], srcl);
            float w0 = __shfl_sync(0xffffffffu, s[ck][0], srcl + 2);
            float w1 = __shfl_sync(0xffffffffu, s[ck][1], srcl + 2);
            float w2 = __shfl_sync(0xffffffffu, s[ck][2], srcl + 2);
            float w3 = __shfl_sync(0xffffffffu, s[ck][3], srcl + 2);
            float aP[4];
            aP[0] = (q & 1) ? u1 : u0;   // P[r0][ck*8+q]
            aP[1] = (q & 1) ? u3 : u2;   // P[r1][ck*8+q]
            aP[2] = (q & 1) ? w1 : w0;   // P[r0][ck*8+q+4]
            aP[3] = (q & 1) ? w3 : w2;   // P[r1][ck*8+q+4]
#pragma unroll
            for (int dt = 0; dt < 8; dt++) {
                float bb[2];
                bb[0] = Vs[ck*8+q][dt*8+g];
                bb[1] = Vs[ck*8+q+4][dt*8+g];
                mma8(o[dt], aP, bb);
            }
        }

        // ---- load next tile (single buffer, 2 syncs) ----
        if (jt < 15) {
            __syncthreads();   // everyone done reading Ks/Vs/pol
            const float* src0 = kb0 + (size_t)((jt + 1) * 64) * QKVD;
#pragma unroll
            for (int p = 0; p < 4; p++) {
                const float* src = src0 + (size_t)(p * 16) * QKVD;
                int r = ldr + p * 16;
                *(float4*)&Ks[r][ldc] = cvt4(*(const float4*)(src));
                *(float4*)&Vs[r][ldc] = cvt4(*(const float4*)(src + DIM_));
            }
            if (tid < 64)
                pol[tid] = policy[(size_t)b * SEQ + (jt+1) * 64 + tid];
            __syncthreads();
        }
    }

    // ---- epilogue ----
    const float inv0 = 1.f / l0, inv1 = 1.f / l1;
    const size_t ro0 = ((size_t)(b * SEQ) + grow0) * DIM_ + h * HD_;
#pragma unroll
    for (int dt = 0; dt < 8; dt++) {
        int c = dt*8 + 2*q;
        *(float2*)&g_att[ro0 + c] =
            make_float2(o[dt][0] * inv0, o[dt][1] * inv0);
        *(float2*)&g_att[ro0 + (size_t)8 * DIM_ + c] =
            make_float2(o[dt][2] * inv1, o[dt][3] * inv1);
    }
}

// ---------------------------------------------------------------------------
extern "C" void kernel_launch(void* const* d_in, const int* in_sizes, int n_in,
                              void* d_out, int out_size)
{
    const float* x      = (const float*)d_in[0];
    const float* policy = (const float*)d_in[1];
    const float* qkv_w  = (const float*)d_in[2];
    const float* proj_w = (const float*)d_in[3];
    const float* proj_b = (const float*)d_in[4];
    float* out = (float*)d_out;

    float* qkv_buf; float* att_buf;
    cudaGetSymbolAddress((void**)&qkv_buf, g_qkv);
    cudaGetSymbolAddress((void**)&att_buf, g_att);

    const int attn_smem = (128*68 + 64*68 + 64*72 + 64) * (int)sizeof(float); // 70912
    cudaFuncSetAttribute(attn_tf32,
                         cudaFuncAttributeMaxDynamicSharedMemorySize, attn_smem);

    // 1) QKV = x @ qkv_w^T
    gemm_tf32<<<dim3(QKVD/128, (B_*SEQ)/128), 256>>>(
        x, qkv_w, nullptr, qkv_buf, B_*SEQ, QKVD, DIM_);
    // 2) Fused policy-softmax attention -> g_att [B*N, H*HD]
    attn_tf32<<<dim3(SEQ/128, NH, B_), 256, attn_smem>>>(policy);
    // 3) out = att @ proj_w^T + proj_b
    gemm_tf32<<<dim3(DIM_/128, (B_*SEQ)/128), 256>>>(
        att_buf, proj_w, proj_b, out, B_*SEQ, DIM_, DIM_);
}